// round 10
// baseline (speedup 1.0000x reference)
#include <cuda_runtime.h>

// Problem constants
#define T_STEPS 500
#define BATCH   1024
#define NDIM    256
#define ALPHA_F 0.995f   // 1 - 0.05/10
#define VTH_F   1.0f

// Chunking (R7 geometry — best measured: DRAM 77.7%)
#define CHUNK_T      20
#define N_CHUNKS     (T_STEPS / CHUNK_T)      // 25
#define ROWS_CHUNK   (CHUNK_T * BATCH)        // 20480 rows / chunk
#define TPB          256
#define C_BLOCKS     4                        // consumer blocks (first in grid)
#define BPC          512                      // producer blocks per chunk
#define ROWS_PB      (ROWS_CHUNK / BPC)       // 40 rows / block
#define ROWS_PW      (ROWS_PB / (TPB / 32))   // 5 rows / warp
#define P_BLOCKS     (N_CHUNKS * BPC)         // 12800 one-shot producer blocks

// Scratch: per-(t,b) input currents (2 MB, L2-resident)
__device__ float g_s[T_STEPS * BATCH];

// Flags padded to one 128B L2 line per chunk (no cross-chunk line sharing)
struct __align__(128) PaddedFlag { unsigned v; unsigned pad[31]; };
__device__ PaddedFlag g_flag[N_CHUNKS];   // #producer blocks done with chunk c
__device__ PaddedFlag g_done[N_CHUNKS];   // #consumer blocks done (self-clean)

__device__ __forceinline__ unsigned ld_acquire_gpu(const unsigned* p) {
    unsigned v;
    asm volatile("ld.acquire.gpu.u32 %0, [%1];" : "=r"(v) : "l"(p) : "memory");
    return v;
}

// single-instruction release add: replaces __threadfence() + atomicAdd()
// (avoids the GPU-scope MEMBAR whose cost scales with in-flight stores)
__device__ __forceinline__ void atom_add_release_gpu(unsigned* p, unsigned v) {
    unsigned old;
    asm volatile("atom.release.gpu.global.add.u32 %0, [%1], %2;"
                 : "=r"(old) : "l"(p), "r"(v) : "memory");
}

__global__ void __launch_bounds__(TPB) lif_fused_kernel(
    const float* __restrict__ x,      // [T, B, N]
    const float* __restrict__ w,      // [N]
    float* __restrict__ out)          // [2, T, B]  (v then z)
{
    const int tid = threadIdx.x;

    if (blockIdx.x >= C_BLOCKS) {
        // ========== PRODUCER (one-shot: 40 rows of one chunk) ==========
        const int pb   = blockIdx.x - C_BLOCKS;   // 0..12799, chunk-major
        const int c    = pb >> 9;                 // pb / 512 : chunk id
        const int slab = pb & 511;                // block-within-chunk
        const int warp = tid >> 5;
        const int lane = tid & 31;

        const long long rbase = (long long)c * ROWS_CHUNK
                              + slab * ROWS_PB + warp * ROWS_PW;

        const float4* wv = reinterpret_cast<const float4*>(w);
        const float4 w0 = wv[lane];
        const float4 w1 = wv[lane + 32];

        float4 a[2 * ROWS_PW];
        #pragma unroll
        for (int i = 0; i < ROWS_PW; ++i) {
            const float4* xr =
                reinterpret_cast<const float4*>(x + (rbase + i) * NDIM);
            a[2 * i]     = xr[lane];
            a[2 * i + 1] = xr[lane + 32];
        }

        float acc[ROWS_PW];
        #pragma unroll
        for (int i = 0; i < ROWS_PW; ++i) {
            const float4 p0 = a[2 * i], p1 = a[2 * i + 1];
            acc[i] = p0.x * w0.x + p0.y * w0.y + p0.z * w0.z + p0.w * w0.w
                   + p1.x * w1.x + p1.y * w1.y + p1.z * w1.z + p1.w * w1.w;
        }
        #pragma unroll
        for (int off = 16; off > 0; off >>= 1) {
            #pragma unroll
            for (int i = 0; i < ROWS_PW; ++i)
                acc[i] += __shfl_xor_sync(0xffffffffu, acc[i], off);
        }
        if (lane == 0) {
            #pragma unroll
            for (int i = 0; i < ROWS_PW; ++i)
                g_s[rbase + i] = acc[i];
        }

        __syncthreads();                  // intra-CTA happens-before edge
        if (tid == 0) {
            // release-add: publishes all CTA stores (HB via barrier) to
            // any observer that acquires the flag. No MEMBAR.
            atom_add_release_gpu(&g_flag[c].v, 1u);
        }
        // block exits; scheduler refills the SM slot with a fresh block
    } else {
        // ================= CONSUMER (persistent, 25 chunks) =================
        const int b = blockIdx.x * TPB + tid;   // 0..1023
        float* __restrict__ vout = out;                               // [T, B]
        float* __restrict__ zout = out + (long long)T_STEPS * BATCH;  // [T, B]

        float v = 0.0f, z = 0.0f;

        #pragma unroll 1
        for (int c = 0; c < N_CHUNKS; ++c) {
            if (tid == 0) {
                while (ld_acquire_gpu(&g_flag[c].v) < BPC) { }
            }
            __syncthreads();   // order all threads after the acquire

            const int tbase = c * CHUNK_T;

            float s[CHUNK_T];
            #pragma unroll
            for (int i = 0; i < CHUNK_T; ++i)
                s[i] = g_s[(tbase + i) * BATCH + b];

            #pragma unroll
            for (int i = 0; i < CHUNK_T; ++i) {
                v = ALPHA_F * v + s[i] - z;
                z = (v > VTH_F) ? 1.0f : 0.0f;
                const int t = tbase + i;
                vout[(long long)t * BATCH + b] = v;
                zout[(long long)t * BATCH + b] = z;
            }

            __syncthreads();
            // self-clean flags for next graph replay: last consumer block resets
            if (tid == 0) {
                if (atomicAdd(&g_done[c].v, 1u) == C_BLOCKS - 1) {
                    g_flag[c].v = 0;
                    g_done[c].v = 0;
                }
            }
        }
    }
}

// ---------------------------------------------------------------------------
extern "C" void kernel_launch(void* const* d_in, const int* in_sizes, int n_in,
                              void* d_out, int out_size)
{
    const float* x = (const float*)d_in[0];   // [T, B, N] fp32
    const float* w = (const float*)d_in[1];   // [N] fp32
    float* out = (float*)d_out;               // [2, T, B] fp32

    lif_fused_kernel<<<C_BLOCKS + P_BLOCKS, TPB>>>(x, w, out);
}

// round 11
// speedup vs baseline: 1.0398x; 1.0398x over previous
#include <cuda_runtime.h>

// Problem constants
#define T_STEPS 500
#define BATCH   1024
#define NDIM    256
#define ALPHA_F 0.995f   // 1 - 0.05/10
#define VTH_F   1.0f

// Chunking
#define CHUNK_T      20
#define N_CHUNKS     (T_STEPS / CHUNK_T)      // 25
#define ROWS_CHUNK   (CHUNK_T * BATCH)        // 20480 rows / chunk
#define TPB          256
#define C_BLOCKS     4                        // consumer blocks (first in grid)
#define BPC          128                      // producer blocks per chunk
#define ROWS_PB      (ROWS_CHUNK / BPC)       // 160 rows / block
#define N_PASS       4                        // inner passes of the R7 body
#define ROWS_PASS    (ROWS_PB / N_PASS)       // 40 rows / pass
#define ROWS_PW      (ROWS_PASS / (TPB / 32)) // 5 rows / warp / pass
#define P_BLOCKS     (N_CHUNKS * BPC)         // 3200 one-shot producer blocks

// Scratch: per-(t,b) input currents (2 MB, L2-resident) + sync flags
__device__ float    g_s[T_STEPS * BATCH];
__device__ unsigned g_flag[N_CHUNKS];   // #producer blocks done with chunk c
__device__ unsigned g_done[N_CHUNKS];   // #consumer blocks done (self-clean)

__device__ __forceinline__ unsigned ld_acquire_gpu(const unsigned* p) {
    unsigned v;
    asm volatile("ld.acquire.gpu.u32 %0, [%1];" : "=r"(v) : "l"(p) : "memory");
    return v;
}

__global__ void __launch_bounds__(TPB) lif_fused_kernel(
    const float* __restrict__ x,      // [T, B, N]
    const float* __restrict__ w,      // [N]
    float* __restrict__ out)          // [2, T, B]  (v then z)
{
    const int tid = threadIdx.x;

    if (blockIdx.x >= C_BLOCKS) {
        // ========== PRODUCER (one-shot: 160 rows of one chunk) ==========
        // 4 sequential passes of the proven R7 warp body (5 rows/warp,
        // 10 independent float4 loads). ONE fence+atomic per 160 rows:
        // sync-signal count drops 12800 -> 3200 vs R7.
        const int pb   = blockIdx.x - C_BLOCKS;   // chunk-major
        const int c    = pb / BPC;                // chunk id
        const int slab = pb % BPC;                // block-within-chunk
        const int warp = tid >> 5;
        const int lane = tid & 31;

        const float4* wv = reinterpret_cast<const float4*>(w);
        const float4 w0 = wv[lane];
        const float4 w1 = wv[lane + 32];

        const long long bbase = (long long)c * ROWS_CHUNK + slab * ROWS_PB;

        #pragma unroll 1
        for (int p = 0; p < N_PASS; ++p) {
            const long long rbase = bbase + p * ROWS_PASS + warp * ROWS_PW;

            float4 a[2 * ROWS_PW];
            #pragma unroll
            for (int i = 0; i < ROWS_PW; ++i) {
                const float4* xr =
                    reinterpret_cast<const float4*>(x + (rbase + i) * NDIM);
                a[2 * i]     = xr[lane];
                a[2 * i + 1] = xr[lane + 32];
            }

            float acc[ROWS_PW];
            #pragma unroll
            for (int i = 0; i < ROWS_PW; ++i) {
                const float4 p0 = a[2 * i], p1 = a[2 * i + 1];
                acc[i] = p0.x * w0.x + p0.y * w0.y + p0.z * w0.z + p0.w * w0.w
                       + p1.x * w1.x + p1.y * w1.y + p1.z * w1.z + p1.w * w1.w;
            }
            #pragma unroll
            for (int off = 16; off > 0; off >>= 1) {
                #pragma unroll
                for (int i = 0; i < ROWS_PW; ++i)
                    acc[i] += __shfl_xor_sync(0xffffffffu, acc[i], off);
            }
            if (lane == 0) {
                #pragma unroll
                for (int i = 0; i < ROWS_PW; ++i)
                    g_s[rbase + i] = acc[i];
            }
        }

        __syncthreads();                  // block's g_s stores complete
        if (tid == 0) {
            __threadfence();              // publish before counting
            atomicAdd(&g_flag[c], 1u);
        }
        // block exits; scheduler refills the SM slot with a fresh block
    } else {
        // ================= CONSUMER (persistent, 25 chunks) =================
        const int b = blockIdx.x * TPB + tid;   // 0..1023
        float* __restrict__ vout = out;                               // [T, B]
        float* __restrict__ zout = out + (long long)T_STEPS * BATCH;  // [T, B]

        float v = 0.0f, z = 0.0f;

        #pragma unroll 1
        for (int c = 0; c < N_CHUNKS; ++c) {
            if (tid == 0) {
                while (ld_acquire_gpu(&g_flag[c]) < BPC) { }
            }
            __syncthreads();   // order all threads after the acquire

            const int tbase = c * CHUNK_T;

            float s[CHUNK_T];
            #pragma unroll
            for (int i = 0; i < CHUNK_T; ++i)
                s[i] = g_s[(tbase + i) * BATCH + b];

            #pragma unroll
            for (int i = 0; i < CHUNK_T; ++i) {
                v = ALPHA_F * v + s[i] - z;
                z = (v > VTH_F) ? 1.0f : 0.0f;
                const int t = tbase + i;
                vout[(long long)t * BATCH + b] = v;
                zout[(long long)t * BATCH + b] = z;
            }

            __syncthreads();
            // self-clean flags for next graph replay: last consumer block resets
            if (tid == 0) {
                if (atomicAdd(&g_done[c], 1u) == C_BLOCKS - 1) {
                    g_flag[c] = 0;
                    g_done[c] = 0;
                }
            }
        }
    }
}

// ---------------------------------------------------------------------------
extern "C" void kernel_launch(void* const* d_in, const int* in_sizes, int n_in,
                              void* d_out, int out_size)
{
    const float* x = (const float*)d_in[0];   // [T, B, N] fp32
    const float* w = (const float*)d_in[1];   // [N] fp32
    float* out = (float*)d_out;               // [2, T, B] fp32

    lif_fused_kernel<<<C_BLOCKS + P_BLOCKS, TPB>>>(x, w, out);
}